// round 1
// baseline (speedup 1.0000x reference)
#include <cuda_runtime.h>
#include <math.h>

#define BATCH 8
#define NTOK 4096
#define DI 512
#define HH 64
#define SROW 65   // padded row stride in shared memory (conflict-free)

// ---------------- device scratch (static: no allocations allowed) ----------------
__device__ float g_part[BATCH * 8 * DI];      // partial pooled sums
__device__ float g_pooled[BATCH * DI];        // pooled means
__device__ float g_dtg[BATCH * DI];           // dt * gamma
__device__ float g_Abuf[(size_t)BATCH * 2 * DI * NTOK];  // [B][2*DI][NTOK]  (128 MB)

// ---------------- pooled mean: partial sums then combine (deterministic) ----------
__global__ void pooled_partial_kernel(const float* __restrict__ x) {
    int b = blockIdx.x;        // batch
    int s = blockIdx.y;        // n-slice of 512
    int d = threadIdx.x;       // channel
    const float* p = x + ((size_t)b * NTOK + (size_t)s * 512) * DI + d;
    float acc = 0.f;
#pragma unroll 8
    for (int n = 0; n < 512; n++) acc += p[(size_t)n * DI];
    g_part[(b * 8 + s) * DI + d] = acc;
}

__global__ void pooled_combine_kernel() {
    int b = blockIdx.x;
    int d = threadIdx.x;
    float acc = 0.f;
#pragma unroll
    for (int s = 0; s < 8; s++) acc += g_part[(b * 8 + s) * DI + d];
    g_pooled[b * DI + d] = acc * (1.0f / (float)NTOK);
}

// ---------------- gamma = min(softplus(pooled @ Wg^T + bg + log_base), 0.35) ------
__global__ void gamma_kernel(const float* __restrict__ Wg,
                             const float* __restrict__ bg,
                             const float* __restrict__ log_base,
                             const int* __restrict__ ks) {
    int b = blockIdx.x;
    int warp = threadIdx.x >> 5, lane = threadIdx.x & 31;
    int d = blockIdx.y * 8 + warp;          // grid.y = 64, 8 warps/block
    const float* wr = Wg + (size_t)d * DI;
    const float* pl = g_pooled + b * DI;
    float acc = 0.f;
    for (int k = lane; k < DI; k += 32) acc += wr[k] * pl[k];
#pragma unroll
    for (int o = 16; o; o >>= 1) acc += __shfl_xor_sync(0xffffffffu, acc, o);
    if (lane == 0) {
        float z = acc + bg[d] + log_base[d];
        float sp = (z > 20.f) ? z : log1pf(expf(z));
        float gm = fminf(sp, 0.35f);
        int k = ks[0]; if (k < 1) k = 1;
        g_dtg[b * DI + d] = gm / (float)k;   // dt * gamma
    }
}

// ---------------- 8-point DFT (DIF, output in bit-reversed register slots) --------
template <int SGN>
__device__ __forceinline__ void dft8(float* xr, float* xi) {
    const float INV = 0.70710678118654752f;
    const float S = (float)SGN;       // -1 forward, +1 inverse
    // stage 1 (span 4) with W8^j twiddles on the difference path
#pragma unroll
    for (int j = 0; j < 4; j++) {
        float ar = xr[j], ai = xi[j], br = xr[j + 4], bi = xi[j + 4];
        float sr = ar + br, si = ai + bi;
        float tr = ar - br, ti = ai - bi;
        float orr, oii;
        if (j == 0)      { orr = tr;                    oii = ti; }
        else if (j == 1) { orr = INV * (tr - S * ti);   oii = INV * (S * tr + ti); }
        else if (j == 2) { orr = -S * ti;               oii = S * tr; }
        else             { orr = -INV * (tr + S * ti);  oii = INV * (S * tr - ti); }
        xr[j] = sr; xi[j] = si; xr[j + 4] = orr; xi[j + 4] = oii;
    }
    // stage 2 (span 2), twiddle W4^1 = (0, S)
#pragma unroll
    for (int gb = 0; gb < 8; gb += 4) {
        { float ar = xr[gb], ai = xi[gb], br = xr[gb + 2], bi = xi[gb + 2];
          xr[gb] = ar + br; xi[gb] = ai + bi; xr[gb + 2] = ar - br; xi[gb + 2] = ai - bi; }
        { float ar = xr[gb + 1], ai = xi[gb + 1], br = xr[gb + 3], bi = xi[gb + 3];
          float tr = ar - br, ti = ai - bi;
          xr[gb + 1] = ar + br; xi[gb + 1] = ai + bi;
          xr[gb + 3] = -S * ti; xi[gb + 3] = S * tr; }
    }
    // stage 3 (span 1)
#pragma unroll
    for (int p = 0; p < 8; p += 2) {
        float ar = xr[p], ai = xi[p], br = xr[p + 1], bi = xi[p + 1];
        xr[p] = ar + br; xi[p] = ai + bi; xr[p + 1] = ar - br; xi[p + 1] = ai - bi;
    }
}

// One 8-wide sub-pass of a 64-pt FFT along a line.
// Reads/writes positions  base + (j*JS + g*GS)*stride,  j = 0..7.
// Output q goes to position with j=q (fetch from bit-reversed slot).
// TW: multiply output q by exp(SGN * 2*pi*i * g*q / 64).
template <int SGN, bool TW, int JS, int GS>
__device__ __forceinline__ void pass8(float* __restrict__ sre, float* __restrict__ sim,
                                      const float* __restrict__ twc, const float* __restrict__ tws,
                                      int base, int stride, int g) {
    const int BR[8] = {0, 4, 2, 6, 1, 5, 3, 7};
    float xr[8], xi[8];
    int p0 = base + g * GS * stride;
#pragma unroll
    for (int j = 0; j < 8; j++) {
        int p = p0 + j * JS * stride;
        xr[j] = sre[p]; xi[j] = sim[p];
    }
    dft8<SGN>(xr, xi);
#pragma unroll
    for (int q = 0; q < 8; q++) {
        int sl = BR[q];
        float yr = xr[sl], yi = xi[sl];
        if (TW) {
            int m = (g * q) & 63;
            float c = twc[m];
            float s = (SGN < 0) ? -tws[m] : tws[m];
            float t = yr * c - yi * s;
            yi = yr * s + yi * c;
            yr = t;
        }
        int p = p0 + q * JS * stride;
        sre[p] = yr; sim[p] = yi;
    }
}

__device__ __forceinline__ void reaction_half(float* __restrict__ sre, float* __restrict__ sim,
                                              int tid, float a, float b2, float ea, float hdt,
                                              bool azero) {
#pragma unroll
    for (int ii = 0; ii < 16; ii++) {
        int i = tid + ii * 256;
        int idx = (i >> 6) * SROW + (i & 63);
        float re = sre[idx], im = sim[idx];
        float q = re * re + im * im;
        float qn;
        if (azero) {
            qn = q / (1.f + b2 * q * hdt);
        } else {
            float den = fmaxf(b2 * q + (a - b2 * q) * ea, 1e-8f);
            qn = a * q / den;
        }
        qn = fmaxf(qn, 0.f);
        float sc = sqrtf(qn / fmaxf(q, 1e-8f));
        sre[idx] = re * sc;
        sim[idx] = im * sc;
    }
}

// ---------------- main per-plane diffusion kernel ---------------------------------
__global__ __launch_bounds__(256) void fft_kernel(const float* __restrict__ x,
                                                  const float* __restrict__ alpha_raw,
                                                  const float* __restrict__ beta_raw,
                                                  const int* __restrict__ ks) {
    __shared__ float sre[HH * SROW];
    __shared__ float sim[HH * SROW];
    __shared__ float twc[64], tws[64], pyc[64], pys[64];
    __shared__ float sh_par[4];   // a, b2, ea, halfdt
    __shared__ int sh_k;

    int tid = threadIdx.x;
    int plane = blockIdx.x;
    int b = plane >> 9;
    int c = plane & (DI - 1);

    if (tid < 64) {
        float ang = 6.283185307179586f * (float)tid / 64.f;
        twc[tid] = cosf(ang);
        tws[tid] = sinf(ang);
        // storage index -> frequency (base-8 digit swap)
        int kr = ((tid & 7) << 3) | (tid >> 3);
        float e = 2.f * cosf(6.283185307179586f * (float)kr / 64.f) - 2.f;
        float dtg = g_dtg[b * DI + c];
        float arg = dtg * e;
        pyc[tid] = cosf(arg);
        pys[tid] = sinf(arg);
    }
    if (tid == 0) {
        int k = ks[0]; if (k < 1) k = 1;
        sh_k = k;
        float dt = 1.f / (float)k;
        float al = 0.25f * tanhf(alpha_raw[c]);
        float br = beta_raw[c];
        float sp = (br > 20.f) ? br : log1pf(expf(br));
        float a = 2.f * al;
        float b2 = 2.f * (sp + 1e-4f);
        sh_par[0] = a;
        sh_par[1] = b2;
        sh_par[2] = expf(-a * 0.5f * dt);
        sh_par[3] = 0.5f * dt;
    }

    // load plane (strided over channels; x is L2-resident after pooled kernel)
    const float* xp = x + (size_t)b * NTOK * DI + c;
#pragma unroll
    for (int ii = 0; ii < 16; ii++) {
        int i = tid + ii * 256;
        sre[(i >> 6) * SROW + (i & 63)] = xp[(size_t)i * DI];
        sim[(i >> 6) * SROW + (i & 63)] = 0.f;
    }
    __syncthreads();

    float a = sh_par[0], b2 = sh_par[1], ea = sh_par[2], hdt = sh_par[3];
    int ksteps = sh_k;
    bool azero = fabsf(a) < 1e-6f;

    for (int step = 0; step < ksteps; step++) {
        reaction_half(sre, sim, tid, a, b2, ea, hdt, azero);
        __syncthreads();

        // forward rows: stage1 (stride-8 + W64 twiddle), stage2 (contig)
#pragma unroll
        for (int it = 0; it < 2; it++) { int t = tid + it * 256; pass8<-1, true, 8, 1>(sre, sim, twc, tws, (t & 63) * SROW, 1, t >> 6); }
        __syncthreads();
#pragma unroll
        for (int it = 0; it < 2; it++) { int t = tid + it * 256; pass8<-1, false, 1, 8>(sre, sim, twc, tws, (t & 63) * SROW, 1, t >> 6); }
        __syncthreads();
        // forward cols
#pragma unroll
        for (int it = 0; it < 2; it++) { int t = tid + it * 256; pass8<-1, true, 8, 1>(sre, sim, twc, tws, (t & 63), SROW, t >> 6); }
        __syncthreads();
#pragma unroll
        for (int it = 0; it < 2; it++) { int t = tid + it * 256; pass8<-1, false, 1, 8>(sre, sim, twc, tws, (t & 63), SROW, t >> 6); }
        __syncthreads();

        // spectral phase multiply (includes 1/4096 inverse-FFT normalization)
#pragma unroll
        for (int ii = 0; ii < 16; ii++) {
            int i = tid + ii * 256;
            int sy = i >> 6, sx = i & 63;
            int idx = sy * SROW + sx;
            float cy = pyc[sy], syv = pys[sy], cx = pyc[sx], sxv = pys[sx];
            float pc = (cy * cx - syv * sxv) * (1.f / 4096.f);
            float ps = (cy * sxv + syv * cx) * (1.f / 4096.f);
            float re = sre[idx], im = sim[idx];
            sre[idx] = re * pc - im * ps;
            sim[idx] = re * ps + im * pc;
        }
        __syncthreads();

        // inverse rows: stageA (contig + conj twiddle), stageB (stride-8)
#pragma unroll
        for (int it = 0; it < 2; it++) { int t = tid + it * 256; pass8<1, true, 1, 8>(sre, sim, twc, tws, (t & 63) * SROW, 1, t >> 6); }
        __syncthreads();
#pragma unroll
        for (int it = 0; it < 2; it++) { int t = tid + it * 256; pass8<1, false, 8, 1>(sre, sim, twc, tws, (t & 63) * SROW, 1, t >> 6); }
        __syncthreads();
        // inverse cols
#pragma unroll
        for (int it = 0; it < 2; it++) { int t = tid + it * 256; pass8<1, true, 1, 8>(sre, sim, twc, tws, (t & 63), SROW, t >> 6); }
        __syncthreads();
#pragma unroll
        for (int it = 0; it < 2; it++) { int t = tid + it * 256; pass8<1, false, 8, 1>(sre, sim, twc, tws, (t & 63), SROW, t >> 6); }
        __syncthreads();

        reaction_half(sre, sim, tid, a, b2, ea, hdt, azero);
        __syncthreads();
    }

    // write combined features [B][2*DI][NTOK]: real at j=c, imag at j=DI+c
    float* Ar = g_Abuf + ((size_t)b * 2 * DI + c) * NTOK;
    float* Ai = g_Abuf + ((size_t)b * 2 * DI + DI + c) * NTOK;
#pragma unroll
    for (int ii = 0; ii < 16; ii++) {
        int i = tid + ii * 256;
        int idx = (i >> 6) * SROW + (i & 63);
        Ar[i] = sre[idx];
        Ai[i] = sim[idx];
    }
}

// ---------------- epilogue GEMM: out[b,n,o] = sum_j A[b,j,n]*Wout[o,j] + x*D -------
__global__ __launch_bounds__(256) void gemm_kernel(const float* __restrict__ Wout,
                                                   const float* __restrict__ x,
                                                   const float* __restrict__ Dp,
                                                   float* __restrict__ out) {
    __shared__ float As[16][128];
    __shared__ float Bs[16][128];
    int b = blockIdx.z;
    int n0 = blockIdx.x * 128;
    int o0 = blockIdx.y * 128;
    const float* A = g_Abuf + (size_t)b * (2 * DI) * NTOK;
    int tid = threadIdx.x;
    int tx = tid & 15, ty = tid >> 4;

    unsigned long long acc[8][4];
#pragma unroll
    for (int i = 0; i < 8; i++)
#pragma unroll
        for (int j = 0; j < 4; j++) acc[i][j] = 0ULL;

    int la_k = tid >> 4, la_c = (tid & 15) * 8;
    int lb_o = tid & 127, lb_kh = (tid >> 7) * 8;

    for (int k0 = 0; k0 < 1024; k0 += 16) {
        float4 av0 = *(const float4*)(A + (size_t)(k0 + la_k) * NTOK + n0 + la_c);
        float4 av1 = *(const float4*)(A + (size_t)(k0 + la_k) * NTOK + n0 + la_c + 4);
        float4 bv0 = *(const float4*)(Wout + (size_t)(o0 + lb_o) * 1024 + k0 + lb_kh);
        float4 bv1 = *(const float4*)(Wout + (size_t)(o0 + lb_o) * 1024 + k0 + lb_kh + 4);

        *(float4*)&As[la_k][la_c] = av0;
        *(float4*)&As[la_k][la_c + 4] = av1;
        Bs[lb_kh + 0][lb_o] = bv0.x; Bs[lb_kh + 1][lb_o] = bv0.y;
        Bs[lb_kh + 2][lb_o] = bv0.z; Bs[lb_kh + 3][lb_o] = bv0.w;
        Bs[lb_kh + 4][lb_o] = bv1.x; Bs[lb_kh + 5][lb_o] = bv1.y;
        Bs[lb_kh + 6][lb_o] = bv1.z; Bs[lb_kh + 7][lb_o] = bv1.w;
        __syncthreads();

#pragma unroll
        for (int kt = 0; kt < 16; kt++) {
            float4 a0 = *(const float4*)&As[kt][ty * 8];
            float4 a1 = *(const float4*)&As[kt][ty * 8 + 4];
            ulonglong2 bq0 = *(const ulonglong2*)&Bs[kt][tx * 8];
            ulonglong2 bq1 = *(const ulonglong2*)&Bs[kt][tx * 8 + 4];
            unsigned long long bp0 = bq0.x, bp1 = bq0.y, bp2 = bq1.x, bp3 = bq1.y;
            float av[8] = {a0.x, a0.y, a0.z, a0.w, a1.x, a1.y, a1.z, a1.w};
#pragma unroll
            for (int i = 0; i < 8; i++) {
                unsigned long long ad;
                asm("mov.b64 %0, {%1, %1};" : "=l"(ad) : "f"(av[i]));
                asm("fma.rn.f32x2 %0, %1, %2, %3;" : "=l"(acc[i][0]) : "l"(ad), "l"(bp0), "l"(acc[i][0]));
                asm("fma.rn.f32x2 %0, %1, %2, %3;" : "=l"(acc[i][1]) : "l"(ad), "l"(bp1), "l"(acc[i][1]));
                asm("fma.rn.f32x2 %0, %1, %2, %3;" : "=l"(acc[i][2]) : "l"(ad), "l"(bp2), "l"(acc[i][2]));
                asm("fma.rn.f32x2 %0, %1, %2, %3;" : "=l"(acc[i][3]) : "l"(ad), "l"(bp3), "l"(acc[i][3]));
            }
        }
        __syncthreads();
    }

    // epilogue: + x * Dparam
    float dpar[8];
#pragma unroll
    for (int j = 0; j < 8; j++) dpar[j] = Dp[o0 + tx * 8 + j];
#pragma unroll
    for (int i = 0; i < 8; i++) {
        int n = n0 + ty * 8 + i;
        size_t rowoff = ((size_t)b * NTOK + n) * DI + o0 + tx * 8;
        const float* xr = x + rowoff;
        float* op = out + rowoff;
        float res[8];
#pragma unroll
        for (int j = 0; j < 4; j++) {
            float lo, hi;
            asm("mov.b64 {%0, %1}, %2;" : "=f"(lo), "=f"(hi) : "l"(acc[i][j]));
            res[2 * j] = lo; res[2 * j + 1] = hi;
        }
#pragma unroll
        for (int j = 0; j < 8; j++) op[j] = res[j] + xr[j] * dpar[j];
    }
}

// ---------------- launch ----------------------------------------------------------
extern "C" void kernel_launch(void* const* d_in, const int* in_sizes, int n_in,
                              void* d_out, int out_size) {
    const float* x         = (const float*)d_in[0];
    const float* Wg        = (const float*)d_in[1];
    const float* bg        = (const float*)d_in[2];
    const float* log_base  = (const float*)d_in[3];
    const float* alpha_raw = (const float*)d_in[4];
    const float* beta_raw  = (const float*)d_in[5];
    const float* Wout      = (const float*)d_in[6];
    const float* Dp        = (const float*)d_in[7];
    const int*   ks        = (const int*)d_in[8];
    float* out = (float*)d_out;

    pooled_partial_kernel<<<dim3(BATCH, 8), DI>>>(x);
    pooled_combine_kernel<<<BATCH, DI>>>();
    gamma_kernel<<<dim3(BATCH, 64), 256>>>(Wg, bg, log_base, ks);
    fft_kernel<<<BATCH * DI, 256>>>(x, alpha_raw, beta_raw, ks);
    gemm_kernel<<<dim3(NTOK / 128, DI / 128, BATCH), 256>>>(Wout, x, Dp, out);
}

// round 2
// speedup vs baseline: 1.2603x; 1.2603x over previous
#include <cuda_runtime.h>
#include <math.h>

#define BATCH 8
#define NTOK 4096
#define DI 512
#define HH 64
#define SROW 65   // padded row stride in shared memory (conflict-free: 65 mod 32 = 1)

// ---------------- device scratch (static: no allocations allowed) ----------------
__device__ float g_part[BATCH * 8 * DI];      // partial pooled sums
__device__ float g_pooled[BATCH * DI];        // pooled means
__device__ float g_dtg[BATCH * DI];           // dt * gamma
__device__ float g_Abuf[(size_t)BATCH * 2 * DI * NTOK];  // [B][2*DI][NTOK]  (128 MB)

// ---------------- pooled mean: partial sums then combine (deterministic) ----------
__global__ void pooled_partial_kernel(const float* __restrict__ x) {
    int b = blockIdx.x;        // batch
    int s = blockIdx.y;        // n-slice of 512
    int d = threadIdx.x;       // channel
    const float* p = x + ((size_t)b * NTOK + (size_t)s * 512) * DI + d;
    float acc = 0.f;
#pragma unroll 8
    for (int n = 0; n < 512; n++) acc += p[(size_t)n * DI];
    g_part[(b * 8 + s) * DI + d] = acc;
}

__global__ void pooled_combine_kernel() {
    int b = blockIdx.x;
    int d = threadIdx.x;
    float acc = 0.f;
#pragma unroll
    for (int s = 0; s < 8; s++) acc += g_part[(b * 8 + s) * DI + d];
    g_pooled[b * DI + d] = acc * (1.0f / (float)NTOK);
}

// ---------------- gamma = min(softplus(pooled @ Wg^T + bg + log_base), 0.35) ------
__global__ void gamma_kernel(const float* __restrict__ Wg,
                             const float* __restrict__ bg,
                             const float* __restrict__ log_base,
                             const int* __restrict__ ks) {
    int b = blockIdx.x;
    int warp = threadIdx.x >> 5, lane = threadIdx.x & 31;
    int d = blockIdx.y * 8 + warp;          // grid.y = 64, 8 warps/block
    const float* wr = Wg + (size_t)d * DI;
    const float* pl = g_pooled + b * DI;
    float acc = 0.f;
    for (int k = lane; k < DI; k += 32) acc += wr[k] * pl[k];
#pragma unroll
    for (int o = 16; o; o >>= 1) acc += __shfl_xor_sync(0xffffffffu, acc, o);
    if (lane == 0) {
        float z = acc + bg[d] + log_base[d];
        float sp = (z > 20.f) ? z : log1pf(expf(z));
        float gm = fminf(sp, 0.35f);
        int k = ks[0]; if (k < 1) k = 1;
        g_dtg[b * DI + d] = gm / (float)k;   // dt * gamma
    }
}

// ---------------- exact reaction update on one complex point ----------------------
__device__ __forceinline__ void react_pt(float& re, float& im,
                                         float a, float b2, float ea, float dt, int azero) {
    float q = re * re + im * im;
    float qn;
    if (azero) {
        qn = q / (1.f + b2 * q * dt);
    } else {
        float den = fmaxf(b2 * q + (a - b2 * q) * ea, 1e-8f);
        qn = fmaxf(a * q / den, 0.f);
    }
    float sc = sqrtf(qn / fmaxf(q, 1e-8f));
    re *= sc; im *= sc;
}

// ---------------- 8-point DFT (DIF, output in bit-reversed register slots) --------
template <int SGN>
__device__ __forceinline__ void dft8(float* xr, float* xi) {
    const float INV = 0.70710678118654752f;
    const float S = (float)SGN;       // -1 forward, +1 inverse
#pragma unroll
    for (int j = 0; j < 4; j++) {
        float ar = xr[j], ai = xi[j], br = xr[j + 4], bi = xi[j + 4];
        float sr = ar + br, si = ai + bi;
        float tr = ar - br, ti = ai - bi;
        float orr, oii;
        if (j == 0)      { orr = tr;                    oii = ti; }
        else if (j == 1) { orr = INV * (tr - S * ti);   oii = INV * (S * tr + ti); }
        else if (j == 2) { orr = -S * ti;               oii = S * tr; }
        else             { orr = -INV * (tr + S * ti);  oii = INV * (S * tr - ti); }
        xr[j] = sr; xi[j] = si; xr[j + 4] = orr; xi[j + 4] = oii;
    }
#pragma unroll
    for (int gb = 0; gb < 8; gb += 4) {
        { float ar = xr[gb], ai = xi[gb], br = xr[gb + 2], bi = xi[gb + 2];
          xr[gb] = ar + br; xi[gb] = ai + bi; xr[gb + 2] = ar - br; xi[gb + 2] = ai - bi; }
        { float ar = xr[gb + 1], ai = xi[gb + 1], br = xr[gb + 3], bi = xi[gb + 3];
          float tr = ar - br, ti = ai - bi;
          xr[gb + 1] = ar + br; xi[gb + 1] = ai + bi;
          xr[gb + 3] = -S * ti; xi[gb + 3] = S * tr; }
    }
#pragma unroll
    for (int p = 0; p < 8; p += 2) {
        float ar = xr[p], ai = xi[p], br = xr[p + 1], bi = xi[p + 1];
        xr[p] = ar + br; xi[p] = ai + bi; xr[p + 1] = ar - br; xi[p + 1] = ai - bi;
    }
}

// One 8-wide sub-pass of a 64-pt FFT along a line, with fused boundary ops.
// LM (load mode):  0 = smem, 1 = smem + reaction, 2 = global x (imag=0) + reaction
// SM (store mode): 0 = smem, 1 = smem + spectral phase (incl 1/4096), 3 = reaction + global store
// aux: for LM==2 it is the line (row) index; for SM==1/3 it is the column index.
template <int SGN, bool TW, int JS, int GS, int LM, int SM>
__device__ __forceinline__ void pass8x(
    float* __restrict__ sre, float* __restrict__ sim,
    const float* __restrict__ twc, const float* __restrict__ tws,
    int base, int stride, int g, int aux,
    float ra, float rb2, float rea, float rdt, int razero,
    const float* __restrict__ pyc, const float* __restrict__ pys,
    const float* __restrict__ gx, float* __restrict__ gAr, float* __restrict__ gAi)
{
    const int BR[8] = {0, 4, 2, 6, 1, 5, 3, 7};
    float xr[8], xi[8];
    int p0 = base + g * GS * stride;
#pragma unroll
    for (int j = 0; j < 8; j++) {
        int e = j * JS + g * GS;
        if (LM == 2) {
            xr[j] = gx[(size_t)(aux * 64 + e) * DI];
            xi[j] = 0.f;
        } else {
            int p = base + e * stride;
            xr[j] = sre[p]; xi[j] = sim[p];
        }
        if (LM >= 1) react_pt(xr[j], xi[j], ra, rb2, rea, rdt, razero);
    }
    dft8<SGN>(xr, xi);
    float cx = 0.f, sxv = 0.f;
    if (SM == 1) { cx = pyc[aux]; sxv = pys[aux]; }
#pragma unroll
    for (int q = 0; q < 8; q++) {
        float yr = xr[BR[q]], yi = xi[BR[q]];
        if (TW) {
            int m = (g * q) & 63;
            float c = twc[m];
            float s = (SGN < 0) ? -tws[m] : tws[m];
            float t = yr * c - yi * s;
            yi = yr * s + yi * c;
            yr = t;
        }
        int e = q * JS + g * GS;
        if (SM == 1) {
            float cy = pyc[e], syv = pys[e];
            float pc = (cy * cx - syv * sxv) * (1.f / 4096.f);
            float ps = (cy * sxv + syv * cx) * (1.f / 4096.f);
            float t = yr * pc - yi * ps;
            yi = yr * ps + yi * pc;
            yr = t;
        }
        if (SM == 3) {
            react_pt(yr, yi, ra, rb2, rea, rdt, razero);
            int lin = e * 64 + aux;
            gAr[lin] = yr; gAi[lin] = yi;
        } else {
            int p = base + e * stride;
            sre[p] = yr; sim[p] = yi;
        }
    }
}

// ---------------- main per-plane diffusion kernel ---------------------------------
__global__ __launch_bounds__(256, 3) void fft_kernel(const float* __restrict__ x,
                                                     const float* __restrict__ alpha_raw,
                                                     const float* __restrict__ beta_raw,
                                                     const int* __restrict__ ks) {
    __shared__ float sre[HH * SROW];
    __shared__ float sim[HH * SROW];
    __shared__ float twc[64], tws[64], pyc[64], pys[64];
    __shared__ float sh_par[6];   // a, b2, ea_h, hdt, ea_f, fdt
    __shared__ int sh_k;

    int tid = threadIdx.x;
    int plane = blockIdx.x;
    int b = plane >> 9;
    int c = plane & (DI - 1);

    if (tid < 64) {
        float ang = 6.283185307179586f * (float)tid / 64.f;
        twc[tid] = cosf(ang);
        tws[tid] = sinf(ang);
        // storage index -> frequency (base-8 digit swap)
        int kr = ((tid & 7) << 3) | (tid >> 3);
        float e = 2.f * cosf(6.283185307179586f * (float)kr / 64.f) - 2.f;
        float dtg = g_dtg[b * DI + c];
        float arg = dtg * e;
        pyc[tid] = cosf(arg);
        pys[tid] = sinf(arg);
    }
    if (tid == 0) {
        int k = ks[0]; if (k < 1) k = 1;
        sh_k = k;
        float dt = 1.f / (float)k;
        float al = 0.25f * tanhf(alpha_raw[c]);
        float br = beta_raw[c];
        float sp = (br > 20.f) ? br : log1pf(expf(br));
        float a = 2.f * al;
        float b2 = 2.f * (sp + 1e-4f);
        sh_par[0] = a;
        sh_par[1] = b2;
        sh_par[2] = expf(-a * 0.5f * dt);
        sh_par[3] = 0.5f * dt;
        sh_par[4] = expf(-a * dt);
        sh_par[5] = dt;
    }
    __syncthreads();

    float a = sh_par[0], b2 = sh_par[1];
    float ea_h = sh_par[2], hdt = sh_par[3];
    float ea_f = sh_par[4], fdt = sh_par[5];
    int ksteps = sh_k;
    int azero = fabsf(a) < 1e-6f;

    const float* xp = x + (size_t)b * NTOK * DI + c;
    float* Ar = g_Abuf + ((size_t)b * 2 * DI + c) * NTOK;
    float* Ai = g_Abuf + ((size_t)b * 2 * DI + DI + c) * NTOK;

#define PASS(SGN, TW, JS, GS, LM, SM, BASE, STRIDE, AUX, REA, RDT)                          \
    {                                                                                       \
        _Pragma("unroll")                                                                   \
        for (int it = 0; it < 2; it++) {                                                    \
            int t = tid + it * 256;                                                         \
            int ln = t & 63, g = t >> 6;                                                    \
            (void)ln;                                                                       \
            pass8x<SGN, TW, JS, GS, LM, SM>(sre, sim, twc, tws, (BASE), (STRIDE), g, (AUX), \
                                            a, b2, (REA), (RDT), azero, pyc, pys,           \
                                            xp, Ar, Ai);                                    \
        }                                                                                   \
    }

    for (int step = 0; step < ksteps; step++) {
        // forward rows stage1 (+reaction at load: step0 pulls straight from global x)
        if (step == 0) {
            PASS(-1, true, 8, 1, 2, 0, ln * SROW, 1, ln, ea_h, hdt);
        } else {
            PASS(-1, true, 8, 1, 1, 0, ln * SROW, 1, ln, ea_f, fdt);
        }
        __syncthreads();
        PASS(-1, false, 1, 8, 0, 0, ln * SROW, 1, 0, 0.f, 0.f);          // fwd rows stage2
        __syncthreads();
        PASS(-1, true, 8, 1, 0, 0, ln, SROW, 0, 0.f, 0.f);               // fwd cols stage1
        __syncthreads();
        PASS(-1, false, 1, 8, 0, 1, ln, SROW, ln, 0.f, 0.f);             // fwd cols stage2 + phase
        __syncthreads();
        PASS(1, true, 1, 8, 0, 0, ln * SROW, 1, 0, 0.f, 0.f);            // inv rows stage1
        __syncthreads();
        PASS(1, false, 8, 1, 0, 0, ln * SROW, 1, 0, 0.f, 0.f);           // inv rows stage2
        __syncthreads();
        PASS(1, true, 1, 8, 0, 0, ln, SROW, 0, 0.f, 0.f);                // inv cols stage1
        __syncthreads();
        if (step == ksteps - 1) {
            // inv cols stage2 + final half-reaction + direct global store
            PASS(1, false, 8, 1, 0, 3, ln, SROW, ln, ea_h, hdt);
        } else {
            PASS(1, false, 8, 1, 0, 0, ln, SROW, 0, 0.f, 0.f);
            __syncthreads();
        }
    }
#undef PASS
}

// ---------------- epilogue GEMM: out[b,n,o] = sum_j A[b,j,n]*Wout[o,j] + x*D -------
__global__ __launch_bounds__(256, 2) void gemm_kernel(const float* __restrict__ Wout,
                                                      const float* __restrict__ x,
                                                      const float* __restrict__ Dp,
                                                      float* __restrict__ out) {
    __shared__ float As[2][16][128];
    __shared__ float Bs[2][16][128];
    int b = blockIdx.z;
    int n0 = blockIdx.x * 128;
    int o0 = blockIdx.y * 128;
    const float* A = g_Abuf + (size_t)b * (2 * DI) * NTOK;
    int tid = threadIdx.x;
    int tx = tid & 15, ty = tid >> 4;

    unsigned long long acc[8][4];
#pragma unroll
    for (int i = 0; i < 8; i++)
#pragma unroll
        for (int j = 0; j < 4; j++) acc[i][j] = 0ULL;

    int la_k = tid >> 4, la_c = (tid & 15) * 8;
    int lb_o = tid & 127, lb_kh = (tid >> 7) * 8;

    // prologue: load tile k0=0 into buffer 0
    {
        float4 av0 = *(const float4*)(A + (size_t)la_k * NTOK + n0 + la_c);
        float4 av1 = *(const float4*)(A + (size_t)la_k * NTOK + n0 + la_c + 4);
        float4 bv0 = *(const float4*)(Wout + (size_t)(o0 + lb_o) * 1024 + lb_kh);
        float4 bv1 = *(const float4*)(Wout + (size_t)(o0 + lb_o) * 1024 + lb_kh + 4);
        *(float4*)&As[0][la_k][la_c] = av0;
        *(float4*)&As[0][la_k][la_c + 4] = av1;
        Bs[0][lb_kh + 0][lb_o] = bv0.x; Bs[0][lb_kh + 1][lb_o] = bv0.y;
        Bs[0][lb_kh + 2][lb_o] = bv0.z; Bs[0][lb_kh + 3][lb_o] = bv0.w;
        Bs[0][lb_kh + 4][lb_o] = bv1.x; Bs[0][lb_kh + 5][lb_o] = bv1.y;
        Bs[0][lb_kh + 6][lb_o] = bv1.z; Bs[0][lb_kh + 7][lb_o] = bv1.w;
    }
    __syncthreads();

    int buf = 0;
    for (int k0 = 0; k0 < 1024; k0 += 16) {
        float4 av0, av1, bv0, bv1;
        bool more = (k0 + 16 < 1024);
        if (more) {
            int kn = k0 + 16;
            av0 = *(const float4*)(A + (size_t)(kn + la_k) * NTOK + n0 + la_c);
            av1 = *(const float4*)(A + (size_t)(kn + la_k) * NTOK + n0 + la_c + 4);
            bv0 = *(const float4*)(Wout + (size_t)(o0 + lb_o) * 1024 + kn + lb_kh);
            bv1 = *(const float4*)(Wout + (size_t)(o0 + lb_o) * 1024 + kn + lb_kh + 4);
        }

#pragma unroll
        for (int kt = 0; kt < 16; kt++) {
            float4 a0 = *(const float4*)&As[buf][kt][ty * 8];
            float4 a1 = *(const float4*)&As[buf][kt][ty * 8 + 4];
            ulonglong2 bq0 = *(const ulonglong2*)&Bs[buf][kt][tx * 8];
            ulonglong2 bq1 = *(const ulonglong2*)&Bs[buf][kt][tx * 8 + 4];
            unsigned long long bp0 = bq0.x, bp1 = bq0.y, bp2 = bq1.x, bp3 = bq1.y;
            float av[8] = {a0.x, a0.y, a0.z, a0.w, a1.x, a1.y, a1.z, a1.w};
#pragma unroll
            for (int i = 0; i < 8; i++) {
                unsigned long long ad;
                asm("mov.b64 %0, {%1, %1};" : "=l"(ad) : "f"(av[i]));
                asm("fma.rn.f32x2 %0, %1, %2, %3;" : "=l"(acc[i][0]) : "l"(ad), "l"(bp0), "l"(acc[i][0]));
                asm("fma.rn.f32x2 %0, %1, %2, %3;" : "=l"(acc[i][1]) : "l"(ad), "l"(bp1), "l"(acc[i][1]));
                asm("fma.rn.f32x2 %0, %1, %2, %3;" : "=l"(acc[i][2]) : "l"(ad), "l"(bp2), "l"(acc[i][2]));
                asm("fma.rn.f32x2 %0, %1, %2, %3;" : "=l"(acc[i][3]) : "l"(ad), "l"(bp3), "l"(acc[i][3]));
            }
        }

        if (more) {
            int nb = buf ^ 1;
            *(float4*)&As[nb][la_k][la_c] = av0;
            *(float4*)&As[nb][la_k][la_c + 4] = av1;
            Bs[nb][lb_kh + 0][lb_o] = bv0.x; Bs[nb][lb_kh + 1][lb_o] = bv0.y;
            Bs[nb][lb_kh + 2][lb_o] = bv0.z; Bs[nb][lb_kh + 3][lb_o] = bv0.w;
            Bs[nb][lb_kh + 4][lb_o] = bv1.x; Bs[nb][lb_kh + 5][lb_o] = bv1.y;
            Bs[nb][lb_kh + 6][lb_o] = bv1.z; Bs[nb][lb_kh + 7][lb_o] = bv1.w;
            __syncthreads();
            buf = nb;
        }
    }

    // epilogue: + x * Dparam
    float dpar[8];
#pragma unroll
    for (int j = 0; j < 8; j++) dpar[j] = Dp[o0 + tx * 8 + j];
#pragma unroll
    for (int i = 0; i < 8; i++) {
        int n = n0 + ty * 8 + i;
        size_t rowoff = ((size_t)b * NTOK + n) * DI + o0 + tx * 8;
        const float* xr = x + rowoff;
        float* op = out + rowoff;
        float res[8];
#pragma unroll
        for (int j = 0; j < 4; j++) {
            float lo, hi;
            asm("mov.b64 {%0, %1}, %2;" : "=f"(lo), "=f"(hi) : "l"(acc[i][j]));
            res[2 * j] = lo; res[2 * j + 1] = hi;
        }
#pragma unroll
        for (int j = 0; j < 8; j++) op[j] = res[j] + xr[j] * dpar[j];
    }
}

// ---------------- launch ----------------------------------------------------------
extern "C" void kernel_launch(void* const* d_in, const int* in_sizes, int n_in,
                              void* d_out, int out_size) {
    const float* x         = (const float*)d_in[0];
    const float* Wg        = (const float*)d_in[1];
    const float* bg        = (const float*)d_in[2];
    const float* log_base  = (const float*)d_in[3];
    const float* alpha_raw = (const float*)d_in[4];
    const float* beta_raw  = (const float*)d_in[5];
    const float* Wout      = (const float*)d_in[6];
    const float* Dp        = (const float*)d_in[7];
    const int*   ks        = (const int*)d_in[8];
    float* out = (float*)d_out;

    pooled_partial_kernel<<<dim3(BATCH, 8), DI>>>(x);
    pooled_combine_kernel<<<BATCH, DI>>>();
    gamma_kernel<<<dim3(BATCH, 64), 256>>>(Wg, bg, log_base, ks);
    fft_kernel<<<BATCH * DI, 256>>>(x, alpha_raw, beta_raw, ks);
    gemm_kernel<<<dim3(NTOK / 128, DI / 128, BATCH), 256>>>(Wout, x, Dp, out);
}

// round 5
// speedup vs baseline: 1.7405x; 1.3810x over previous
#include <cuda_runtime.h>
#include <cuda_bf16.h>
#include <math.h>
#include <cstdint>

#define BATCH 8
#define NTOK 4096
#define DI 512
#define HH 64
#define SROW 65   // padded row stride in shared memory (conflict-free: 65 mod 32 = 1)

// ---------------- device scratch (static: no allocations allowed) ----------------
__device__ float g_part[BATCH * 8 * DI];
__device__ float g_pooled[BATCH * DI];
__device__ float g_dtg[BATCH * DI];
__device__ float g_Abuf[(size_t)BATCH * 2 * DI * NTOK];            // [B][k=1024][n=4096] fp32
__device__ __nv_bfloat16 g_Ath[(size_t)BATCH * NTOK * 2 * DI];     // [B][n][k] bf16 hi
__device__ __nv_bfloat16 g_Atl[(size_t)BATCH * NTOK * 2 * DI];     // [B][n][k] bf16 lo
__device__ __nv_bfloat16 g_Wh[DI * 2 * DI];                        // [o][k] bf16 hi
__device__ __nv_bfloat16 g_Wl[DI * 2 * DI];                        // [o][k] bf16 lo

// ---------------- pooled mean ------------------------------------------------------
__global__ void pooled_partial_kernel(const float* __restrict__ x) {
    int b = blockIdx.x, s = blockIdx.y, d = threadIdx.x;
    const float* p = x + ((size_t)b * NTOK + (size_t)s * 512) * DI + d;
    float acc = 0.f;
#pragma unroll 8
    for (int n = 0; n < 512; n++) acc += p[(size_t)n * DI];
    g_part[(b * 8 + s) * DI + d] = acc;
}
__global__ void pooled_combine_kernel() {
    int b = blockIdx.x, d = threadIdx.x;
    float acc = 0.f;
#pragma unroll
    for (int s = 0; s < 8; s++) acc += g_part[(b * 8 + s) * DI + d];
    g_pooled[b * DI + d] = acc * (1.0f / (float)NTOK);
}

// ---------------- gamma -----------------------------------------------------------
__global__ void gamma_kernel(const float* __restrict__ Wg,
                             const float* __restrict__ bg,
                             const float* __restrict__ log_base,
                             const int* __restrict__ ks) {
    int b = blockIdx.x;
    int warp = threadIdx.x >> 5, lane = threadIdx.x & 31;
    int d = blockIdx.y * 8 + warp;
    const float* wr = Wg + (size_t)d * DI;
    const float* pl = g_pooled + b * DI;
    float acc = 0.f;
    for (int k = lane; k < DI; k += 32) acc += wr[k] * pl[k];
#pragma unroll
    for (int o = 16; o; o >>= 1) acc += __shfl_xor_sync(0xffffffffu, acc, o);
    if (lane == 0) {
        float z = acc + bg[d] + log_base[d];
        float sp = (z > 20.f) ? z : log1pf(expf(z));
        float gm = fminf(sp, 0.35f);
        int k = ks[0]; if (k < 1) k = 1;
        g_dtg[b * DI + d] = gm / (float)k;
    }
}

// ---------------- exact reaction update -------------------------------------------
__device__ __forceinline__ void react_pt(float& re, float& im,
                                         float a, float b2, float ea, float dt, int azero) {
    float q = re * re + im * im;
    float qn;
    if (azero) {
        qn = q / (1.f + b2 * q * dt);
    } else {
        float den = fmaxf(b2 * q + (a - b2 * q) * ea, 1e-8f);
        qn = fmaxf(a * q / den, 0.f);
    }
    float sc = sqrtf(qn / fmaxf(q, 1e-8f));
    re *= sc; im *= sc;
}

// ---------------- 8-point DFT -----------------------------------------------------
template <int SGN>
__device__ __forceinline__ void dft8(float* xr, float* xi) {
    const float INV = 0.70710678118654752f;
    const float S = (float)SGN;
#pragma unroll
    for (int j = 0; j < 4; j++) {
        float ar = xr[j], ai = xi[j], br = xr[j + 4], bi = xi[j + 4];
        float sr = ar + br, si = ai + bi;
        float tr = ar - br, ti = ai - bi;
        float orr, oii;
        if (j == 0)      { orr = tr;                    oii = ti; }
        else if (j == 1) { orr = INV * (tr - S * ti);   oii = INV * (S * tr + ti); }
        else if (j == 2) { orr = -S * ti;               oii = S * tr; }
        else             { orr = -INV * (tr + S * ti);  oii = INV * (S * tr - ti); }
        xr[j] = sr; xi[j] = si; xr[j + 4] = orr; xi[j + 4] = oii;
    }
#pragma unroll
    for (int gb = 0; gb < 8; gb += 4) {
        { float ar = xr[gb], ai = xi[gb], br = xr[gb + 2], bi = xi[gb + 2];
          xr[gb] = ar + br; xi[gb] = ai + bi; xr[gb + 2] = ar - br; xi[gb + 2] = ai - bi; }
        { float ar = xr[gb + 1], ai = xi[gb + 1], br = xr[gb + 3], bi = xi[gb + 3];
          float tr = ar - br, ti = ai - bi;
          xr[gb + 1] = ar + br; xi[gb + 1] = ai + bi;
          xr[gb + 3] = -S * ti; xi[gb + 3] = S * tr; }
    }
#pragma unroll
    for (int p = 0; p < 8; p += 2) {
        float ar = xr[p], ai = xi[p], br = xr[p + 1], bi = xi[p + 1];
        xr[p] = ar + br; xi[p] = ai + bi; xr[p + 1] = ar - br; xi[p + 1] = ai - bi;
    }
}

// One 8-wide sub-pass of a 64-pt FFT along a line, with fused boundary ops.
template <int SGN, bool TW, int JS, int GS, int LM, int SM>
__device__ __forceinline__ void pass8x(
    float* __restrict__ sre, float* __restrict__ sim,
    const float* __restrict__ twc, const float* __restrict__ tws,
    int base, int stride, int g, int aux,
    float ra, float rb2, float rea, float rdt, int razero,
    const float* __restrict__ pyc, const float* __restrict__ pys,
    const float* __restrict__ gx, float* __restrict__ gAr, float* __restrict__ gAi)
{
    const int BR[8] = {0, 4, 2, 6, 1, 5, 3, 7};
    float xr[8], xi[8];
#pragma unroll
    for (int j = 0; j < 8; j++) {
        int e = j * JS + g * GS;
        if (LM == 2) {
            xr[j] = gx[(size_t)(aux * 64 + e) * DI];
            xi[j] = 0.f;
        } else {
            int p = base + e * stride;
            xr[j] = sre[p]; xi[j] = sim[p];
        }
        if (LM >= 1) react_pt(xr[j], xi[j], ra, rb2, rea, rdt, razero);
    }
    dft8<SGN>(xr, xi);
    float cx = 0.f, sxv = 0.f;
    if (SM == 1) { cx = pyc[aux]; sxv = pys[aux]; }
#pragma unroll
    for (int q = 0; q < 8; q++) {
        float yr = xr[BR[q]], yi = xi[BR[q]];
        if (TW) {
            int m = (g * q) & 63;
            float c = twc[m];
            float s = (SGN < 0) ? -tws[m] : tws[m];
            float t = yr * c - yi * s;
            yi = yr * s + yi * c;
            yr = t;
        }
        int e = q * JS + g * GS;
        if (SM == 1) {
            float cy = pyc[e], syv = pys[e];
            float pc = (cy * cx - syv * sxv) * (1.f / 4096.f);
            float ps = (cy * sxv + syv * cx) * (1.f / 4096.f);
            float t = yr * pc - yi * ps;
            yi = yr * ps + yi * pc;
            yr = t;
        }
        if (SM == 3) {
            react_pt(yr, yi, ra, rb2, rea, rdt, razero);
            int lin = e * 64 + aux;
            gAr[lin] = yr; gAi[lin] = yi;
        } else {
            int p = base + e * stride;
            sre[p] = yr; sim[p] = yi;
        }
    }
}

// ---------------- main per-plane diffusion kernel ---------------------------------
__global__ __launch_bounds__(256, 3) void fft_kernel(const float* __restrict__ x,
                                                     const float* __restrict__ alpha_raw,
                                                     const float* __restrict__ beta_raw,
                                                     const int* __restrict__ ks) {
    __shared__ float sre[HH * SROW];
    __shared__ float sim[HH * SROW];
    __shared__ float twc[64], tws[64], pyc[64], pys[64];
    __shared__ float sh_par[6];
    __shared__ int sh_k;

    int tid = threadIdx.x;
    int plane = blockIdx.x;
    int b = plane >> 9;
    int c = plane & (DI - 1);

    if (tid < 64) {
        float ang = 6.283185307179586f * (float)tid / 64.f;
        twc[tid] = cosf(ang);
        tws[tid] = sinf(ang);
        int kr = ((tid & 7) << 3) | (tid >> 3);
        float e = 2.f * cosf(6.283185307179586f * (float)kr / 64.f) - 2.f;
        float dtg = g_dtg[b * DI + c];
        float arg = dtg * e;
        pyc[tid] = cosf(arg);
        pys[tid] = sinf(arg);
    }
    if (tid == 0) {
        int k = ks[0]; if (k < 1) k = 1;
        sh_k = k;
        float dt = 1.f / (float)k;
        float al = 0.25f * tanhf(alpha_raw[c]);
        float br = beta_raw[c];
        float sp = (br > 20.f) ? br : log1pf(expf(br));
        float a = 2.f * al;
        float b2 = 2.f * (sp + 1e-4f);
        sh_par[0] = a;
        sh_par[1] = b2;
        sh_par[2] = expf(-a * 0.5f * dt);
        sh_par[3] = 0.5f * dt;
        sh_par[4] = expf(-a * dt);
        sh_par[5] = dt;
    }
    __syncthreads();

    float a = sh_par[0], b2 = sh_par[1];
    float ea_h = sh_par[2], hdt = sh_par[3];
    float ea_f = sh_par[4], fdt = sh_par[5];
    int ksteps = sh_k;
    int azero = fabsf(a) < 1e-6f;

    const float* xp = x + (size_t)b * NTOK * DI + c;
    float* Ar = g_Abuf + ((size_t)b * 2 * DI + c) * NTOK;
    float* Ai = g_Abuf + ((size_t)b * 2 * DI + DI + c) * NTOK;

#define PASS(SGN, TW, JS, GS, LM, SM, BASE, STRIDE, AUX, REA, RDT)                          \
    {                                                                                       \
        _Pragma("unroll")                                                                   \
        for (int it = 0; it < 2; it++) {                                                    \
            int t = tid + it * 256;                                                         \
            int ln = t & 63, g = t >> 6;                                                    \
            (void)ln;                                                                       \
            pass8x<SGN, TW, JS, GS, LM, SM>(sre, sim, twc, tws, (BASE), (STRIDE), g, (AUX), \
                                            a, b2, (REA), (RDT), azero, pyc, pys,           \
                                            xp, Ar, Ai);                                    \
        }                                                                                   \
    }

    for (int step = 0; step < ksteps; step++) {
        if (step == 0) {
            PASS(-1, true, 8, 1, 2, 0, ln * SROW, 1, ln, ea_h, hdt);
        } else {
            PASS(-1, true, 8, 1, 1, 0, ln * SROW, 1, ln, ea_f, fdt);
        }
        __syncthreads();
        PASS(-1, false, 1, 8, 0, 0, ln * SROW, 1, 0, 0.f, 0.f);
        __syncthreads();
        PASS(-1, true, 8, 1, 0, 0, ln, SROW, 0, 0.f, 0.f);
        __syncthreads();
        PASS(-1, false, 1, 8, 0, 1, ln, SROW, ln, 0.f, 0.f);
        __syncthreads();
        PASS(1, true, 1, 8, 0, 0, ln * SROW, 1, 0, 0.f, 0.f);
        __syncthreads();
        PASS(1, false, 8, 1, 0, 0, ln * SROW, 1, 0, 0.f, 0.f);
        __syncthreads();
        PASS(1, true, 1, 8, 0, 0, ln, SROW, 0, 0.f, 0.f);
        __syncthreads();
        if (step == ksteps - 1) {
            PASS(1, false, 8, 1, 0, 3, ln, SROW, ln, ea_h, hdt);
        } else {
            PASS(1, false, 8, 1, 0, 0, ln, SROW, 0, 0.f, 0.f);
            __syncthreads();
        }
    }
#undef PASS
}

// ---------------- transpose + bf16 hi/lo split: [b][k][n] f32 -> [b][n][k] bf16 ---
__global__ __launch_bounds__(256) void transpose_split_kernel() {
    __shared__ float t[32][33];
    int b = blockIdx.z;
    int n0 = blockIdx.x * 32;
    int k0 = blockIdx.y * 32;
    int tx = threadIdx.x, ty = threadIdx.y;   // (32, 8)
    const float* src = g_Abuf + ((size_t)b * 1024 + k0) * NTOK + n0;
#pragma unroll
    for (int r = 0; r < 4; r++)
        t[ty + r * 8][tx] = src[(size_t)(ty + r * 8) * NTOK + tx];
    __syncthreads();
    size_t dbase = ((size_t)b * NTOK + n0) * 1024 + k0;
#pragma unroll
    for (int r = 0; r < 4; r++) {
        float v = t[tx][ty + r * 8];
        __nv_bfloat16 h = __float2bfloat16(v);
        __nv_bfloat16 l = __float2bfloat16(v - __bfloat162float(h));
        size_t di = dbase + (size_t)(ty + r * 8) * 1024 + tx;
        g_Ath[di] = h;
        g_Atl[di] = l;
    }
}

// ---------------- Wout fp32 -> bf16 hi/lo -----------------------------------------
__global__ void wconv_kernel(const float* __restrict__ Wout) {
    int i = blockIdx.x * blockDim.x + threadIdx.x;
    if (i < DI * 2 * DI) {
        float v = Wout[i];
        __nv_bfloat16 h = __float2bfloat16(v);
        g_Wh[i] = h;
        g_Wl[i] = __float2bfloat16(v - __bfloat162float(h));
    }
}

// ================= mma.sync bf16 GEMM =============================================
// out[b, n, o] = sum_k A[b,n,k] * W[o,k] + x*Dp,  via Ah*Wh + Ah*Wl + Al*Wh.
// CTA tile: M=128 (n), N=64 (o), K chunks of 64. 8 warps in 4x2, warp tile 32x32.
#define BK 64
#define AH_OFF 0
#define AL_OFF 16384
#define WH_OFF 32768
#define WL_OFF 40960
#define STAGE_B 49152

__device__ __forceinline__ uint32_t smem_u32(const void* p) {
    uint32_t a;
    asm("{ .reg .u64 t; cvta.to.shared.u64 t, %1; cvt.u32.u64 %0, t; }" : "=r"(a) : "l"(p));
    return a;
}
__device__ __forceinline__ void cp16(uint32_t dst, const void* src) {
    asm volatile("cp.async.cg.shared.global [%0], [%1], 16;" :: "r"(dst), "l"(src));
}
__device__ __forceinline__ void ldsm4(uint32_t* r, uint32_t addr) {
    asm volatile("ldmatrix.sync.aligned.m8n8.x4.shared.b16 {%0,%1,%2,%3}, [%4];"
                 : "=r"(r[0]), "=r"(r[1]), "=r"(r[2]), "=r"(r[3]) : "r"(addr));
}
__device__ __forceinline__ void mma16816(float* c, const uint32_t* a, uint32_t b0, uint32_t b1) {
    asm volatile("mma.sync.aligned.m16n8k16.row.col.f32.bf16.bf16.f32 "
                 "{%0,%1,%2,%3}, {%4,%5,%6,%7}, {%8,%9}, {%0,%1,%2,%3};"
                 : "+f"(c[0]), "+f"(c[1]), "+f"(c[2]), "+f"(c[3])
                 : "r"(a[0]), "r"(a[1]), "r"(a[2]), "r"(a[3]), "r"(b0), "r"(b1));
}
__device__ __forceinline__ uint32_t swz(uint32_t off) { return off ^ ((off >> 3) & 0x70); }

__global__ __launch_bounds__(256) void mma_gemm_kernel(const float* __restrict__ x,
                                                       const float* __restrict__ Dp,
                                                       float* __restrict__ out) {
    extern __shared__ char dsmem_raw[];
    uint32_t raw = smem_u32(dsmem_raw);
    uint32_t base = (raw + 1023u) & ~1023u;

    int tid = threadIdx.x;
    int wid = tid >> 5, lid = tid & 31;
    int wm = wid >> 1, wn = wid & 1;          // warp grid 4 (M) x 2 (N)
    int n0 = blockIdx.x * 128;
    int o0 = blockIdx.y * 64;
    int b = blockIdx.z;

    const __nv_bfloat16* gAh = g_Ath + ((size_t)b * NTOK + n0) * 1024;
    const __nv_bfloat16* gAl = g_Atl + ((size_t)b * NTOK + n0) * 1024;
    const __nv_bfloat16* gWh = g_Wh + (size_t)o0 * 1024;
    const __nv_bfloat16* gWl = g_Wl + (size_t)o0 * 1024;

    // loader mapping
    int ra = tid >> 1, hf = tid & 1;          // A: 2 threads/row, 4x16B each
    int rw = tid >> 2, qw = tid & 3;          // W: 4 threads/row, 2x16B each

#define ISSUE_CHUNK(kc0, stg)                                                              \
    {                                                                                      \
        uint32_t sb = base + (uint32_t)(stg) * STAGE_B;                                    \
        _Pragma("unroll")                                                                  \
        for (int i = 0; i < 4; i++) {                                                      \
            int c16 = hf * 4 + i;                                                          \
            uint32_t so = swz((uint32_t)(ra * 128 + c16 * 16));                            \
            cp16(sb + AH_OFF + so, gAh + (size_t)ra * 1024 + (kc0) + c16 * 8);             \
            cp16(sb + AL_OFF + so, gAl + (size_t)ra * 1024 + (kc0) + c16 * 8);             \
        }                                                                                  \
        _Pragma("unroll")                                                                  \
        for (int i = 0; i < 2; i++) {                                                      \
            int c16 = qw * 2 + i;                                                          \
            uint32_t so = swz((uint32_t)(rw * 128 + c16 * 16));                            \
            cp16(sb + WH_OFF + so, gWh + (size_t)rw * 1024 + (kc0) + c16 * 8);             \
            cp16(sb + WL_OFF + so, gWl + (size_t)rw * 1024 + (kc0) + c16 * 8);             \
        }                                                                                  \
        asm volatile("cp.async.commit_group;");                                            \
    }

    float acc[2][4][4];
#pragma unroll
    for (int m = 0; m < 2; m++)
#pragma unroll
        for (int nf = 0; nf < 4; nf++)
#pragma unroll
            for (int r = 0; r < 4; r++) acc[m][nf][r] = 0.f;

    ISSUE_CHUNK(0, 0);
    asm volatile("cp.async.wait_group 0;" ::: "memory");
    __syncthreads();

    int sub = lid >> 3, l7 = lid & 7;
    int arow_b = wm * 32 + (sub & 1) * 8 + l7;        // + m*16
    int akb_b = (sub >> 1) * 16;                      // + kk*32
    int wrow_b = wn * 32 + (sub >> 1) * 8 + l7;       // + np*16
    int wkb_b = (sub & 1) * 16;                       // + kk*32

    for (int ch = 0; ch < 16; ch++) {
        int stg = ch & 1;
        if (ch + 1 < 16) ISSUE_CHUNK((ch + 1) * BK, stg ^ 1);

        uint32_t sb = base + (uint32_t)stg * STAGE_B;
#pragma unroll
        for (int kk = 0; kk < 4; kk++) {
            uint32_t ah[2][4], al[2][4], wh[2][4], wl[2][4];
#pragma unroll
            for (int m = 0; m < 2; m++) {
                uint32_t off = swz((uint32_t)((arow_b + m * 16) * 128 + kk * 32 + akb_b));
                ldsm4(ah[m], sb + AH_OFF + off);
                ldsm4(al[m], sb + AL_OFF + off);
            }
#pragma unroll
            for (int np = 0; np < 2; np++) {
                uint32_t off = swz((uint32_t)((wrow_b + np * 16) * 128 + kk * 32 + wkb_b));
                ldsm4(wh[np], sb + WH_OFF + off);
                ldsm4(wl[np], sb + WL_OFF + off);
            }
#pragma unroll
            for (int m = 0; m < 2; m++)
#pragma unroll
                for (int nf = 0; nf < 4; nf++) {
                    uint32_t bh0 = wh[nf >> 1][(nf & 1) * 2], bh1 = wh[nf >> 1][(nf & 1) * 2 + 1];
                    uint32_t bl0 = wl[nf >> 1][(nf & 1) * 2], bl1 = wl[nf >> 1][(nf & 1) * 2 + 1];
                    mma16816(acc[m][nf], ah[m], bh0, bh1);
                    mma16816(acc[m][nf], ah[m], bl0, bl1);
                    mma16816(acc[m][nf], al[m], bh0, bh1);
                }
        }

        if (ch + 1 < 16) {
            asm volatile("cp.async.wait_group 0;" ::: "memory");
            __syncthreads();
        }
    }
#undef ISSUE_CHUNK

    // epilogue: out = acc + x * Dp
    int g = lid >> 2, tg = lid & 3;
    float2 dv[4];
#pragma unroll
    for (int nf = 0; nf < 4; nf++)
        dv[nf] = *(const float2*)(Dp + o0 + wn * 32 + nf * 8 + tg * 2);
#pragma unroll
    for (int m = 0; m < 2; m++)
#pragma unroll
        for (int rr = 0; rr < 2; rr++) {
            int row = n0 + wm * 32 + m * 16 + g + rr * 8;
            size_t rowoff = ((size_t)b * NTOK + row) * DI;
#pragma unroll
            for (int nf = 0; nf < 4; nf++) {
                int col = o0 + wn * 32 + nf * 8 + tg * 2;
                const float2 xv = *(const float2*)(x + rowoff + col);
                float2 ov;
                ov.x = acc[m][nf][rr * 2 + 0] + xv.x * dv[nf].x;
                ov.y = acc[m][nf][rr * 2 + 1] + xv.y * dv[nf].y;
                *(float2*)(out + rowoff + col) = ov;
            }
        }
}

// ---------------- launch ----------------------------------------------------------
extern "C" void kernel_launch(void* const* d_in, const int* in_sizes, int n_in,
                              void* d_out, int out_size) {
    const float* x         = (const float*)d_in[0];
    const float* Wg        = (const float*)d_in[1];
    const float* bg        = (const float*)d_in[2];
    const float* log_base  = (const float*)d_in[3];
    const float* alpha_raw = (const float*)d_in[4];
    const float* beta_raw  = (const float*)d_in[5];
    const float* Wout      = (const float*)d_in[6];
    const float* Dp        = (const float*)d_in[7];
    const int*   ks        = (const int*)d_in[8];
    float* out = (float*)d_out;

    int dyn = 2 * STAGE_B + 1024;
    cudaFuncSetAttribute(mma_gemm_kernel, cudaFuncAttributeMaxDynamicSharedMemorySize, dyn);

    pooled_partial_kernel<<<dim3(BATCH, 8), DI>>>(x);
    pooled_combine_kernel<<<BATCH, DI>>>();
    gamma_kernel<<<dim3(BATCH, 64), 256>>>(Wg, bg, log_base, ks);
    wconv_kernel<<<(DI * 2 * DI + 255) / 256, 256>>>(Wout);
    fft_kernel<<<BATCH * DI, 256>>>(x, alpha_raw, beta_raw, ks);
    transpose_split_kernel<<<dim3(NTOK / 32, 1024 / 32, BATCH), dim3(32, 8)>>>();
    mma_gemm_kernel<<<dim3(NTOK / 128, DI / 64, BATCH), 256, dyn>>>(x, Dp, out);
}

// round 6
// speedup vs baseline: 1.9202x; 1.1032x over previous
#include <cuda_runtime.h>
#include <cuda_bf16.h>
#include <math.h>
#include <cstdint>

#define BATCH 8
#define NTOK 4096
#define DI 512
#define HH 64
#define SROWC 65   // padded row stride in COMPLEX (float2) units: 65*2 words -> 2-way max on 64-bit

// ---------------- device scratch (static: no allocations allowed) ----------------
__device__ float g_part[BATCH * 8 * DI];
__device__ float g_pooled[BATCH * DI];
__device__ float g_dtg[BATCH * DI];
__device__ float g_Abuf[(size_t)BATCH * 2 * DI * NTOK];            // [B][k=1024][n=4096] fp32
__device__ __nv_bfloat16 g_Ath[(size_t)BATCH * NTOK * 2 * DI];     // [B][n][k] bf16 hi
__device__ __nv_bfloat16 g_Atl[(size_t)BATCH * NTOK * 2 * DI];     // [B][n][k] bf16 lo
__device__ __nv_bfloat16 g_Wh[DI * 2 * DI];                        // [o][k] bf16 hi
__device__ __nv_bfloat16 g_Wl[DI * 2 * DI];                        // [o][k] bf16 lo

// ---------------- pooled mean ------------------------------------------------------
__global__ void pooled_partial_kernel(const float* __restrict__ x) {
    int b = blockIdx.x, s = blockIdx.y, d = threadIdx.x;
    const float* p = x + ((size_t)b * NTOK + (size_t)s * 512) * DI + d;
    float acc = 0.f;
#pragma unroll 8
    for (int n = 0; n < 512; n++) acc += p[(size_t)n * DI];
    g_part[(b * 8 + s) * DI + d] = acc;
}
__global__ void pooled_combine_kernel() {
    int b = blockIdx.x, d = threadIdx.x;
    float acc = 0.f;
#pragma unroll
    for (int s = 0; s < 8; s++) acc += g_part[(b * 8 + s) * DI + d];
    g_pooled[b * DI + d] = acc * (1.0f / (float)NTOK);
}

// ---------------- gamma -----------------------------------------------------------
__global__ void gamma_kernel(const float* __restrict__ Wg,
                             const float* __restrict__ bg,
                             const float* __restrict__ log_base,
                             const int* __restrict__ ks) {
    int b = blockIdx.x;
    int warp = threadIdx.x >> 5, lane = threadIdx.x & 31;
    int d = blockIdx.y * 8 + warp;
    const float* wr = Wg + (size_t)d * DI;
    const float* pl = g_pooled + b * DI;
    float acc = 0.f;
    for (int k = lane; k < DI; k += 32) acc += wr[k] * pl[k];
#pragma unroll
    for (int o = 16; o; o >>= 1) acc += __shfl_xor_sync(0xffffffffu, acc, o);
    if (lane == 0) {
        float z = acc + bg[d] + log_base[d];
        float sp = (z > 20.f) ? z : log1pf(expf(z));
        float gm = fminf(sp, 0.35f);
        int k = ks[0]; if (k < 1) k = 1;
        g_dtg[b * DI + d] = gm / (float)k;
    }
}

// ---------------- exact reaction update -------------------------------------------
__device__ __forceinline__ void react_pt(float& re, float& im,
                                         float a, float b2, float ea, float dt, int azero) {
    float q = re * re + im * im;
    float qn;
    if (azero) {
        qn = q / (1.f + b2 * q * dt);
    } else {
        float den = fmaxf(b2 * q + (a - b2 * q) * ea, 1e-8f);
        qn = fmaxf(a * q / den, 0.f);
    }
    float sc = sqrtf(qn / fmaxf(q, 1e-8f));
    re *= sc; im *= sc;
}

// ---------------- 8-point DFT on float2 (DIF, bit-reversed output slots) ----------
template <int SGN>
__device__ __forceinline__ void dft8f2(float2* v) {
    const float INV = 0.70710678118654752f;
    const float S = (float)SGN;
#pragma unroll
    for (int j = 0; j < 4; j++) {
        float2 a = v[j], b = v[j + 4];
        float sr = a.x + b.x, si = a.y + b.y;
        float tr = a.x - b.x, ti = a.y - b.y;
        float orr, oii;
        if (j == 0)      { orr = tr;                    oii = ti; }
        else if (j == 1) { orr = INV * (tr - S * ti);   oii = INV * (S * tr + ti); }
        else if (j == 2) { orr = -S * ti;               oii = S * tr; }
        else             { orr = -INV * (tr + S * ti);  oii = INV * (S * tr - ti); }
        v[j] = make_float2(sr, si);
        v[j + 4] = make_float2(orr, oii);
    }
#pragma unroll
    for (int gb = 0; gb < 8; gb += 4) {
        { float2 a = v[gb], b = v[gb + 2];
          v[gb] = make_float2(a.x + b.x, a.y + b.y);
          v[gb + 2] = make_float2(a.x - b.x, a.y - b.y); }
        { float2 a = v[gb + 1], b = v[gb + 3];
          float tr = a.x - b.x, ti = a.y - b.y;
          v[gb + 1] = make_float2(a.x + b.x, a.y + b.y);
          v[gb + 3] = make_float2(-S * ti, S * tr); }
    }
#pragma unroll
    for (int p = 0; p < 8; p += 2) {
        float2 a = v[p], b = v[p + 1];
        v[p] = make_float2(a.x + b.x, a.y + b.y);
        v[p + 1] = make_float2(a.x - b.x, a.y - b.y);
    }
}

// One 8-wide sub-pass of a 64-pt FFT along a line, with fused boundary ops.
// LM: 0 = tile, 1 = tile + reaction, 2 = global x (imag=0) + reaction
// SM: 0 = tile, 1 = tile + spectral phase (incl 1/4096), 3 = reaction + global store
template <int SGN, bool TW, int JS, int GS, int LM, int SM>
__device__ __forceinline__ void pass8x(
    float2* __restrict__ tile, const float2* __restrict__ tw,
    int base, int stride, int g, int aux,
    float ra, float rb2, float rea, float rdt, int razero,
    const float2* __restrict__ py,
    const float* __restrict__ gx, float* __restrict__ gAr, float* __restrict__ gAi)
{
    const int BR[8] = {0, 4, 2, 6, 1, 5, 3, 7};
    float2 v[8];
#pragma unroll
    for (int j = 0; j < 8; j++) {
        int e = j * JS + g * GS;
        if (LM == 2) {
            v[j] = make_float2(gx[(size_t)(aux * 64 + e) * DI], 0.f);
        } else {
            v[j] = tile[base + e * stride];
        }
        if (LM >= 1) react_pt(v[j].x, v[j].y, ra, rb2, rea, rdt, razero);
    }
    dft8f2<SGN>(v);
    float2 px = make_float2(0.f, 0.f);
    if (SM == 1) px = py[aux];
#pragma unroll
    for (int q = 0; q < 8; q++) {
        float2 y = v[BR[q]];
        if (TW) {
            int m = (g * q) & 63;
            float2 w = tw[m];
            float s = (SGN < 0) ? -w.y : w.y;
            float t = y.x * w.x - y.y * s;
            y.y = y.x * s + y.y * w.x;
            y.x = t;
        }
        int e = q * JS + g * GS;
        if (SM == 1) {
            float2 pe = py[e];
            float pc = (pe.x * px.x - pe.y * px.y) * (1.f / 4096.f);
            float ps = (pe.x * px.y + pe.y * px.x) * (1.f / 4096.f);
            float t = y.x * pc - y.y * ps;
            y.y = y.x * ps + y.y * pc;
            y.x = t;
        }
        if (SM == 3) {
            react_pt(y.x, y.y, ra, rb2, rea, rdt, razero);
            int lin = e * 64 + aux;
            gAr[lin] = y.x; gAi[lin] = y.y;
        } else {
            tile[base + e * stride] = y;
        }
    }
}

// ---------------- main per-plane diffusion kernel ---------------------------------
__global__ __launch_bounds__(256, 4) void fft_kernel(const float* __restrict__ x,
                                                     const float* __restrict__ alpha_raw,
                                                     const float* __restrict__ beta_raw,
                                                     const int* __restrict__ ks) {
    __shared__ float2 tile[HH * SROWC];
    __shared__ float2 tw[64], py[64];
    __shared__ float sh_par[6];
    __shared__ int sh_k;

    int tid = threadIdx.x;
    int plane = blockIdx.x;
    int b = plane >> 9;
    int c = plane & (DI - 1);

    if (tid < 64) {
        float ang = 6.283185307179586f * (float)tid / 64.f;
        tw[tid] = make_float2(cosf(ang), sinf(ang));
        int kr = ((tid & 7) << 3) | (tid >> 3);   // storage index -> frequency
        float e = 2.f * cosf(6.283185307179586f * (float)kr / 64.f) - 2.f;
        float dtg = g_dtg[b * DI + c];
        float arg = dtg * e;
        py[tid] = make_float2(cosf(arg), sinf(arg));
    }
    if (tid == 0) {
        int k = ks[0]; if (k < 1) k = 1;
        sh_k = k;
        float dt = 1.f / (float)k;
        float al = 0.25f * tanhf(alpha_raw[c]);
        float br = beta_raw[c];
        float sp = (br > 20.f) ? br : log1pf(expf(br));
        float a = 2.f * al;
        float b2 = 2.f * (sp + 1e-4f);
        sh_par[0] = a;
        sh_par[1] = b2;
        sh_par[2] = expf(-a * 0.5f * dt);
        sh_par[3] = 0.5f * dt;
        sh_par[4] = expf(-a * dt);
        sh_par[5] = dt;
    }
    __syncthreads();

    float a = sh_par[0], b2 = sh_par[1];
    float ea_h = sh_par[2], hdt = sh_par[3];
    float ea_f = sh_par[4], fdt = sh_par[5];
    int ksteps = sh_k;
    int azero = fabsf(a) < 1e-6f;

    const float* xp = x + (size_t)b * NTOK * DI + c;
    float* Ar = g_Abuf + ((size_t)b * 2 * DI + c) * NTOK;
    float* Ai = g_Abuf + ((size_t)b * 2 * DI + DI + c) * NTOK;

#define PASS(SGN, TW, JS, GS, LM, SM, BASE, STRIDE, AUX, REA, RDT)                          \
    {                                                                                       \
        _Pragma("unroll")                                                                   \
        for (int it = 0; it < 2; it++) {                                                    \
            int t = tid + it * 256;                                                         \
            int ln = t & 63, g = t >> 6;                                                    \
            (void)ln;                                                                       \
            pass8x<SGN, TW, JS, GS, LM, SM>(tile, tw, (BASE), (STRIDE), g, (AUX),           \
                                            a, b2, (REA), (RDT), azero, py,                 \
                                            xp, Ar, Ai);                                    \
        }                                                                                   \
    }

    for (int step = 0; step < ksteps; step++) {
        // forward rows stage1 (+reaction at load: step0 pulls straight from global x)
        if (step == 0) {
            PASS(-1, true, 8, 1, 2, 0, ln * SROWC, 1, ln, ea_h, hdt);
        } else {
            PASS(-1, true, 8, 1, 1, 0, ln * SROWC, 1, ln, ea_f, fdt);
        }
        __syncthreads();
        PASS(-1, false, 1, 8, 0, 0, ln * SROWC, 1, 0, 0.f, 0.f);          // fwd rows stage2
        __syncthreads();
        PASS(-1, true, 8, 1, 0, 0, ln, SROWC, 0, 0.f, 0.f);               // fwd cols stage1
        __syncthreads();
        PASS(-1, false, 1, 8, 0, 1, ln, SROWC, ln, 0.f, 0.f);             // fwd cols stage2 + phase
        __syncthreads();
        PASS(1, true, 1, 8, 0, 0, ln * SROWC, 1, 0, 0.f, 0.f);            // inv rows stage1
        __syncthreads();
        PASS(1, false, 8, 1, 0, 0, ln * SROWC, 1, 0, 0.f, 0.f);           // inv rows stage2
        __syncthreads();
        PASS(1, true, 1, 8, 0, 0, ln, SROWC, 0, 0.f, 0.f);                // inv cols stage1
        __syncthreads();
        if (step == ksteps - 1) {
            PASS(1, false, 8, 1, 0, 3, ln, SROWC, ln, ea_h, hdt);         // + react + global store
        } else {
            PASS(1, false, 8, 1, 0, 0, ln, SROWC, 0, 0.f, 0.f);
            __syncthreads();
        }
    }
#undef PASS
}

// ---------------- transpose + bf16 hi/lo split: [b][k][n] f32 -> [b][n][k] bf16 ---
__global__ __launch_bounds__(256) void transpose_split_kernel() {
    __shared__ float t[32][33];
    int b = blockIdx.z;
    int n0 = blockIdx.x * 32;
    int k0 = blockIdx.y * 32;
    int tx = threadIdx.x, ty = threadIdx.y;   // (32, 8)
    const float* src = g_Abuf + ((size_t)b * 1024 + k0) * NTOK + n0;
#pragma unroll
    for (int r = 0; r < 4; r++)
        t[ty + r * 8][tx] = src[(size_t)(ty + r * 8) * NTOK + tx];
    __syncthreads();
    size_t dbase = ((size_t)b * NTOK + n0) * 1024 + k0;
#pragma unroll
    for (int r = 0; r < 4; r++) {
        float v = t[tx][ty + r * 8];
        __nv_bfloat16 h = __float2bfloat16(v);
        __nv_bfloat16 l = __float2bfloat16(v - __bfloat162float(h));
        size_t di = dbase + (size_t)(ty + r * 8) * 1024 + tx;
        g_Ath[di] = h;
        g_Atl[di] = l;
    }
}

// ---------------- Wout fp32 -> bf16 hi/lo -----------------------------------------
__global__ void wconv_kernel(const float* __restrict__ Wout) {
    int i = blockIdx.x * blockDim.x + threadIdx.x;
    if (i < DI * 2 * DI) {
        float v = Wout[i];
        __nv_bfloat16 h = __float2bfloat16(v);
        g_Wh[i] = h;
        g_Wl[i] = __float2bfloat16(v - __bfloat162float(h));
    }
}

// ================= mma.sync bf16 GEMM =============================================
// out[b, n, o] = sum_k A[b,n,k] * W[o,k] + x*Dp,  via Ah*Wh + Ah*Wl + Al*Wh.
// CTA tile: M=128 (n), N=64 (o), K chunks of 64. 8 warps in 4x2, warp tile 32x32.
#define BK 64
#define AH_OFF 0
#define AL_OFF 16384
#define WH_OFF 32768
#define WL_OFF 40960
#define STAGE_B 49152

__device__ __forceinline__ uint32_t smem_u32(const void* p) {
    uint32_t a;
    asm("{ .reg .u64 t; cvta.to.shared.u64 t, %1; cvt.u32.u64 %0, t; }" : "=r"(a) : "l"(p));
    return a;
}
__device__ __forceinline__ void cp16(uint32_t dst, const void* src) {
    asm volatile("cp.async.cg.shared.global [%0], [%1], 16;" :: "r"(dst), "l"(src));
}
__device__ __forceinline__ void ldsm4(uint32_t* r, uint32_t addr) {
    asm volatile("ldmatrix.sync.aligned.m8n8.x4.shared.b16 {%0,%1,%2,%3}, [%4];"
                 : "=r"(r[0]), "=r"(r[1]), "=r"(r[2]), "=r"(r[3]) : "r"(addr));
}
__device__ __forceinline__ void mma16816(float* c, const uint32_t* a, uint32_t b0, uint32_t b1) {
    asm volatile("mma.sync.aligned.m16n8k16.row.col.f32.bf16.bf16.f32 "
                 "{%0,%1,%2,%3}, {%4,%5,%6,%7}, {%8,%9}, {%0,%1,%2,%3};"
                 : "+f"(c[0]), "+f"(c[1]), "+f"(c[2]), "+f"(c[3])
                 : "r"(a[0]), "r"(a[1]), "r"(a[2]), "r"(a[3]), "r"(b0), "r"(b1));
}
__device__ __forceinline__ uint32_t swz(uint32_t off) { return off ^ ((off >> 3) & 0x70); }

__global__ __launch_bounds__(256) void mma_gemm_kernel(const float* __restrict__ x,
                                                       const float* __restrict__ Dp,
                                                       float* __restrict__ out) {
    extern __shared__ char dsmem_raw[];
    uint32_t raw = smem_u32(dsmem_raw);
    uint32_t base = (raw + 1023u) & ~1023u;

    int tid = threadIdx.x;
    int wid = tid >> 5, lid = tid & 31;
    int wm = wid >> 1, wn = wid & 1;          // warp grid 4 (M) x 2 (N)
    int n0 = blockIdx.x * 128;
    int o0 = blockIdx.y * 64;
    int b = blockIdx.z;

    const __nv_bfloat16* gAh = g_Ath + ((size_t)b * NTOK + n0) * 1024;
    const __nv_bfloat16* gAl = g_Atl + ((size_t)b * NTOK + n0) * 1024;
    const __nv_bfloat16* gWh = g_Wh + (size_t)o0 * 1024;
    const __nv_bfloat16* gWl = g_Wl + (size_t)o0 * 1024;

    // loader mapping
    int ra = tid >> 1, hf = tid & 1;          // A: 2 threads/row, 4x16B each
    int rw = tid >> 2, qw = tid & 3;          // W: 4 threads/row, 2x16B each

#define ISSUE_CHUNK(kc0, stg)                                                              \
    {                                                                                      \
        uint32_t sb = base + (uint32_t)(stg) * STAGE_B;                                    \
        _Pragma("unroll")                                                                  \
        for (int i = 0; i < 4; i++) {                                                      \
            int c16 = hf * 4 + i;                                                          \
            uint32_t so = swz((uint32_t)(ra * 128 + c16 * 16));                            \
            cp16(sb + AH_OFF + so, gAh + (size_t)ra * 1024 + (kc0) + c16 * 8);             \
            cp16(sb + AL_OFF + so, gAl + (size_t)ra * 1024 + (kc0) + c16 * 8);             \
        }                                                                                  \
        _Pragma("unroll")                                                                  \
        for (int i = 0; i < 2; i++) {                                                      \
            int c16 = qw * 2 + i;                                                          \
            uint32_t so = swz((uint32_t)(rw * 128 + c16 * 16));                            \
            cp16(sb + WH_OFF + so, gWh + (size_t)rw * 1024 + (kc0) + c16 * 8);             \
            cp16(sb + WL_OFF + so, gWl + (size_t)rw * 1024 + (kc0) + c16 * 8);             \
        }                                                                                  \
        asm volatile("cp.async.commit_group;");                                            \
    }

    float acc[2][4][4];
#pragma unroll
    for (int m = 0; m < 2; m++)
#pragma unroll
        for (int nf = 0; nf < 4; nf++)
#pragma unroll
            for (int r = 0; r < 4; r++) acc[m][nf][r] = 0.f;

    ISSUE_CHUNK(0, 0);
    asm volatile("cp.async.wait_group 0;" ::: "memory");
    __syncthreads();

    int sub = lid >> 3, l7 = lid & 7;
    int arow_b = wm * 32 + (sub & 1) * 8 + l7;        // + m*16
    int akb_b = (sub >> 1) * 16;                      // + kk*32
    int wrow_b = wn * 32 + (sub >> 1) * 8 + l7;       // + np*16
    int wkb_b = (sub & 1) * 16;                       // + kk*32

    for (int ch = 0; ch < 16; ch++) {
        int stg = ch & 1;
        if (ch + 1 < 16) ISSUE_CHUNK((ch + 1) * BK, stg ^ 1);

        uint32_t sb = base + (uint32_t)stg * STAGE_B;
#pragma unroll
        for (int kk = 0; kk < 4; kk++) {
            uint32_t ah[2][4], al[2][4], wh[2][4], wl[2][4];
#pragma unroll
            for (int m = 0; m < 2; m++) {
                uint32_t off = swz((uint32_t)((arow_b + m * 16) * 128 + kk * 32 + akb_b));
                ldsm4(ah[m], sb + AH_OFF + off);
                ldsm4(al[m], sb + AL_OFF + off);
            }
#pragma unroll
            for (int np = 0; np < 2; np++) {
                uint32_t off = swz((uint32_t)((wrow_b + np * 16) * 128 + kk * 32 + wkb_b));
                ldsm4(wh[np], sb + WH_OFF + off);
                ldsm4(wl[np], sb + WL_OFF + off);
            }
#pragma unroll
            for (int m = 0; m < 2; m++)
#pragma unroll
                for (int nf = 0; nf < 4; nf++) {
                    uint32_t bh0 = wh[nf >> 1][(nf & 1) * 2], bh1 = wh[nf >> 1][(nf & 1) * 2 + 1];
                    uint32_t bl0 = wl[nf >> 1][(nf & 1) * 2], bl1 = wl[nf >> 1][(nf & 1) * 2 + 1];
                    mma16816(acc[m][nf], ah[m], bh0, bh1);
                    mma16816(acc[m][nf], ah[m], bl0, bl1);
                    mma16816(acc[m][nf], al[m], bh0, bh1);
                }
        }

        if (ch + 1 < 16) {
            asm volatile("cp.async.wait_group 0;" ::: "memory");
            __syncthreads();
        }
    }
#undef ISSUE_CHUNK

    // epilogue: out = acc + x * Dp
    int g = lid >> 2, tg = lid & 3;
    float2 dv[4];
#pragma unroll
    for (int nf = 0; nf < 4; nf++)
        dv[nf] = *(const float2*)(Dp + o0 + wn * 32 + nf * 8 + tg * 2);
#pragma unroll
    for (int m = 0; m < 2; m++)
#pragma unroll
        for (int rr = 0; rr < 2; rr++) {
            int row = n0 + wm * 32 + m * 16 + g + rr * 8;
            size_t rowoff = ((size_t)b * NTOK + row) * DI;
#pragma unroll
            for (int nf = 0; nf < 4; nf++) {
                int col = o0 + wn * 32 + nf * 8 + tg * 2;
                const float2 xv = *(const float2*)(x + rowoff + col);
                float2 ov;
                ov.x = acc[m][nf][rr * 2 + 0] + xv.x * dv[nf].x;
                ov.y = acc[m][nf][rr * 2 + 1] + xv.y * dv[nf].y;
                *(float2*)(out + rowoff + col) = ov;
            }
        }
}

// ---------------- launch ----------------------------------------------------------
extern "C" void kernel_launch(void* const* d_in, const int* in_sizes, int n_in,
                              void* d_out, int out_size) {
    const float* x         = (const float*)d_in[0];
    const float* Wg        = (const float*)d_in[1];
    const float* bg        = (const float*)d_in[2];
    const float* log_base  = (const float*)d_in[3];
    const float* alpha_raw = (const float*)d_in[4];
    const float* beta_raw  = (const float*)d_in[5];
    const float* Wout      = (const float*)d_in[6];
    const float* Dp        = (const float*)d_in[7];
    const int*   ks        = (const int*)d_in[8];
    float* out = (float*)d_out;

    int dyn = 2 * STAGE_B + 1024;
    cudaFuncSetAttribute(mma_gemm_kernel, cudaFuncAttributeMaxDynamicSharedMemorySize, dyn);

    pooled_partial_kernel<<<dim3(BATCH, 8), DI>>>(x);
    pooled_combine_kernel<<<BATCH, DI>>>();
    gamma_kernel<<<dim3(BATCH, 64), 256>>>(Wg, bg, log_base, ks);
    wconv_kernel<<<(DI * 2 * DI + 255) / 256, 256>>>(Wout);
    fft_kernel<<<BATCH * DI, 256>>>(x, alpha_raw, beta_raw, ks);
    transpose_split_kernel<<<dim3(NTOK / 32, 1024 / 32, BATCH), dim3(32, 8)>>>();
    mma_gemm_kernel<<<dim3(NTOK / 128, DI / 64, BATCH), 256, dyn>>>(x, Dp, out);
}